// round 1
// baseline (speedup 1.0000x reference)
#include <cuda_runtime.h>
#include <math.h>

#define Bb   4
#define Ss   512
#define Ee   512
#define Hh   8
#define DHd  64
#define HIDh 128

// ---- scratch (allocation-free: __device__ globals) ----
__device__ float g_q[Bb*Ss*Ee];
__device__ float g_k[Bb*Ss*Ee];
__device__ float g_v[Bb*Ss*Ee];
__device__ float g_scores[(size_t)Bb*Hh*Ss*Ss];   // also reused for probs
__device__ float g_mean[(size_t)Bb*Ss*Ss];
__device__ float g_tpre[(size_t)Bb*Ss*Ss];
__device__ float g_ctx[Bb*Ss*Ee];
__device__ float g_partial[Bb*Ss*4];
__device__ float g_Acoef[Bb];
__device__ float g_Ccoef[Bb];

// ---------------- reductions ----------------
__device__ __forceinline__ float warp_sum(float v) {
#pragma unroll
    for (int o = 16; o; o >>= 1) v += __shfl_xor_sync(0xffffffffu, v, o);
    return v;
}
__device__ __forceinline__ float warp_max(float v) {
#pragma unroll
    for (int o = 16; o; o >>= 1) v = fmaxf(v, __shfl_xor_sync(0xffffffffu, v, o));
    return v;
}
template <int NW>
__device__ __forceinline__ float block_sum(float v, float* red) {
    int lane = threadIdx.x & 31, w = threadIdx.x >> 5;
    v = warp_sum(v);
    if (lane == 0) red[w] = v;
    __syncthreads();
    if (w == 0) {
        float x = (lane < NW) ? red[lane] : 0.f;
        x = warp_sum(x);
        if (lane == 0) red[0] = x;
    }
    __syncthreads();
    float r = red[0];
    __syncthreads();
    return r;
}
template <int NW>
__device__ __forceinline__ float block_max(float v, float* red) {
    int lane = threadIdx.x & 31, w = threadIdx.x >> 5;
    v = warp_max(v);
    if (lane == 0) red[w] = v;
    __syncthreads();
    if (w == 0) {
        float x = (lane < NW) ? red[lane] : -3.402823e38f;
        x = warp_max(x);
        if (lane == 0) red[0] = x;
    }
    __syncthreads();
    float r = red[0];
    __syncthreads();
    return r;
}

// ---------------- GEMM: C[m,n] = (sum_k A[m,k]*W[n,k] + bias[n]) * scale ----------------
// M = 2048, N = 512, K = 512.  grid(N/64, M/64), block 256.
__global__ __launch_bounds__(256) void gemm_proj(
    const float* __restrict__ A, const float* __restrict__ W,
    const float* __restrict__ bias, float* __restrict__ C, float scale)
{
    __shared__ float As[16][64];
    __shared__ float Bs[16][64];
    const int K = Ee, N = Ee;
    int bm = blockIdx.y * 64, bn = blockIdx.x * 64;
    int tid = threadIdx.x;
    int tm = tid >> 4, tn = tid & 15;
    float acc[4][4] = {};
    for (int k0 = 0; k0 < K; k0 += 16) {
#pragma unroll
        for (int r = 0; r < 4; r++) {
            int idx = tid + r * 256;
            int i = idx >> 4, kk = idx & 15;
            As[kk][i] = A[(size_t)(bm + i) * K + k0 + kk];
            Bs[kk][i] = W[(size_t)(bn + i) * K + k0 + kk];
        }
        __syncthreads();
#pragma unroll
        for (int kk = 0; kk < 16; kk++) {
            float a[4], b[4];
#pragma unroll
            for (int i = 0; i < 4; i++) a[i] = As[kk][tm * 4 + i];
#pragma unroll
            for (int j = 0; j < 4; j++) b[j] = Bs[kk][tn * 4 + j];
#pragma unroll
            for (int i = 0; i < 4; i++)
#pragma unroll
                for (int j = 0; j < 4; j++) acc[i][j] += a[i] * b[j];
        }
        __syncthreads();
    }
#pragma unroll
    for (int i = 0; i < 4; i++)
#pragma unroll
        for (int j = 0; j < 4; j++) {
            int m = bm + tm * 4 + i, n = bn + tn * 4 + j;
            C[(size_t)m * N + n] = (acc[i][j] + bias[n]) * scale;
        }
}

// ---------------- scores[b,h,i,j] = clip(sum_d q*k, -15, 15) ----------------
// grid(8,8,32) block 256
__global__ __launch_bounds__(256) void gemm_scores()
{
    __shared__ float As[16][64];
    __shared__ float Bs[16][64];
    int bh = blockIdx.z;
    int b = bh >> 3, h = bh & 7;
    const float* Ap = g_q + ((size_t)b * Ss) * Ee + h * DHd;
    const float* Bp = g_k + ((size_t)b * Ss) * Ee + h * DHd;
    float* Cp = g_scores + (size_t)bh * Ss * Ss;
    int bm = blockIdx.y * 64, bn = blockIdx.x * 64;
    int tid = threadIdx.x;
    int tm = tid >> 4, tn = tid & 15;
    float acc[4][4] = {};
    for (int k0 = 0; k0 < DHd; k0 += 16) {
#pragma unroll
        for (int r = 0; r < 4; r++) {
            int idx = tid + r * 256;
            int i = idx >> 4, kk = idx & 15;
            As[kk][i] = Ap[(size_t)(bm + i) * Ee + k0 + kk];
            Bs[kk][i] = Bp[(size_t)(bn + i) * Ee + k0 + kk];
        }
        __syncthreads();
#pragma unroll
        for (int kk = 0; kk < 16; kk++) {
            float a[4], bb[4];
#pragma unroll
            for (int i = 0; i < 4; i++) a[i] = As[kk][tm * 4 + i];
#pragma unroll
            for (int j = 0; j < 4; j++) bb[j] = Bs[kk][tn * 4 + j];
#pragma unroll
            for (int i = 0; i < 4; i++)
#pragma unroll
                for (int j = 0; j < 4; j++) acc[i][j] += a[i] * bb[j];
        }
        __syncthreads();
    }
#pragma unroll
    for (int i = 0; i < 4; i++)
#pragma unroll
        for (int j = 0; j < 4; j++) {
            int m = bm + tm * 4 + i, n = bn + tn * 4 + j;
            Cp[(size_t)m * Ss + n] = fminf(fmaxf(acc[i][j], -15.f), 15.f);
        }
}

// ---------------- mean over heads ----------------
__global__ __launch_bounds__(256) void mean_heads_kernel()
{
    int idx = blockIdx.x * 256 + threadIdx.x;   // over Bb*Ss*Ss = 1048576
    int b = idx >> 18;                          // / (Ss*Ss)
    int ij = idx & (Ss * Ss - 1);
    float s = 0.f;
#pragma unroll
    for (int h = 0; h < Hh; h++)
        s += g_scores[((size_t)(b * Hh + h)) * Ss * Ss + ij];
    g_mean[idx] = s * (1.0f / Hh);
}

// ---------------- per-row transform: t_pre + per-row stats ----------------
// grid Bb*Ss=2048, block 512 (thread j)
__global__ __launch_bounds__(512) void transform_kernel(
    const float* __restrict__ w1, const float* __restrict__ b1,
    const float* __restrict__ w2, const float* __restrict__ b2p)
{
    __shared__ float red[16];
    __shared__ float sw1[HIDh], sb1[HIDh], sw2[HIDh];
    int row = blockIdx.x;
    int j = threadIdx.x;
    if (j < HIDh) { sw1[j] = w1[j]; sb1[j] = b1[j]; sw2[j] = w2[j]; }
    __syncthreads();

    float mv = g_mean[(size_t)row * Ss + j];

    // pointwise "autopoietic" scalar function
    float scaled = fminf(fmaxf(mv, -8.f), 8.f) * 0.05f;   // |.|<=0.4, outer clip no-op
    float av = 0.f;
#pragma unroll 8
    for (int hh = 0; hh < HIDh; hh++) {
        float hv = scaled * sw1[hh] + sb1[hh];
        hv = fminf(fmaxf(hv, 0.f), 5.f);                   // relu(clip(-5,5))
        av += hv * sw2[hh];
    }
    av += b2p[0];
    av = fminf(fmaxf(av, -5.f), 5.f);
    float taylor = fminf(fmaxf(1.f + 2.5f * av, 0.5f), 1.5f);
    float sig = 1.f / (1.f + __expf(-taylor));

    // p = softmax(clip(mv,-10,10)); entropy; Fm = softmax(3*H)
    float mc = fminf(fmaxf(mv, -10.f), 10.f);
    float M1 = block_max<16>(mc, red);
    float e1 = __expf(mc - M1);
    float S1 = block_sum<16>(e1, red);
    float p = e1 / S1;
    float Hent = -p * __logf(p + 1e-6f);
    float h3 = 3.f * Hent;
    float M2 = block_max<16>(h3, red);
    float e2 = __expf(h3 - M2);
    float S2 = block_sum<16>(e2, red);

    float t = sig * (e2 / S2);
    g_tpre[(size_t)row * Ss + j] = t;

    float s_m  = block_sum<16>(mv, red);
    float s_m2 = block_sum<16>(mv * mv, red);
    float s_t  = block_sum<16>(t, red);
    float s_t2 = block_sum<16>(t * t, red);
    if (j == 0) {
        g_partial[row * 4 + 0] = s_m;
        g_partial[row * 4 + 1] = s_m2;
        g_partial[row * 4 + 2] = s_t;
        g_partial[row * 4 + 3] = s_t2;
    }
}

// ---------------- per-batch scalars A,C ----------------
// grid Bb, block 512
__global__ __launch_bounds__(512) void scalars_kernel()
{
    __shared__ float red[16];
    int b = blockIdx.x;
    int t = threadIdx.x;
    const float* pr = g_partial + (size_t)(b * Ss + t) * 4;
    float s0 = block_sum<16>(pr[0], red);
    float s1 = block_sum<16>(pr[1], red);
    float s2 = block_sum<16>(pr[2], red);
    float s3 = block_sum<16>(pr[3], red);
    if (t == 0) {
        const float N = (float)(Ss * Ss);
        float e_o = sqrtf(s1) + 1e-4f;
        float e_t = sqrtf(s3) + 1e-4f;
        float gamma = fminf(fmaxf(e_o / e_t, 0.8f), 1.2f);
        float mu_t = s2 / N, mu_o = s0 / N;
        float var_t = gamma * gamma * (s3 / N - mu_t * mu_t);
        float t_std = sqrtf(fmaxf(var_t, 0.01f));
        float var_o = s1 / N - mu_o * mu_o;
        float o_std = sqrtf(fmaxf(var_o, 0.01f));
        float gdyn = fminf(fmaxf(o_std / t_std, 0.8f), 1.2f);
        float A = gdyn * gamma;
        g_Acoef[b] = A;
        g_Ccoef[b] = mu_o - A * mu_t;
    }
}

// ---------------- blend + softmax (in place on g_scores) ----------------
// grid Bb*Hh*Ss = 16384, block 256
__global__ __launch_bounds__(256) void softmax_kernel()
{
    __shared__ float red[8];
    __shared__ float sm[Ss];
    int rowid = blockIdx.x;
    int b = rowid >> 12;        // / (Hh*Ss)
    int i = rowid & (Ss - 1);
    float* srow = g_scores + (size_t)rowid * Ss;
    const float* trow = g_tpre + ((size_t)(b * Ss) + i) * Ss;
    float A = g_Acoef[b], C = g_Ccoef[b];

    float lm = -3.402823e38f;
    for (int j = threadIdx.x; j < Ss; j += 256) {
        float s = srow[j];
        float tt = A * trow[j] + C;
        s = fminf(fmaxf(s + 0.1f * tt, -15.f), 15.f);
        sm[j] = s;
        lm = fmaxf(lm, s);
    }
    float M = block_max<8>(lm, red);
    float ls = 0.f;
    for (int j = threadIdx.x; j < Ss; j += 256) {
        float e = __expf(sm[j] - M);
        sm[j] = e;
        ls += e;
    }
    float Sm = block_sum<8>(ls, red);
    float inv = 1.f / Sm;
    for (int j = threadIdx.x; j < Ss; j += 256)
        srow[j] = sm[j] * inv;
}

// ---------------- ctx[b,i,h*64+d] = sum_j P[b,h,i,j] * v[b,j,h*64+d] ----------------
// grid(8, 32) block 256
__global__ __launch_bounds__(256) void attnv_kernel()
{
    __shared__ float As[16][64];
    __shared__ float Bs[16][64];
    int bh = blockIdx.y;
    int b = bh >> 3, h = bh & 7;
    const float* P = g_scores + (size_t)bh * Ss * Ss;
    const float* Vp = g_v + ((size_t)b * Ss) * Ee + h * DHd;
    float* Cp = g_ctx + ((size_t)b * Ss) * Ee + h * DHd;
    int bm = blockIdx.x * 64;
    int tid = threadIdx.x;
    int tm = tid >> 4, tn = tid & 15;
    float acc[4][4] = {};
    for (int k0 = 0; k0 < Ss; k0 += 16) {
#pragma unroll
        for (int r = 0; r < 4; r++) {
            int idx = tid + r * 256;
            int i = idx >> 4, kk = idx & 15;
            As[kk][i] = P[(size_t)(bm + i) * Ss + k0 + kk];
            int kk2 = idx >> 6, d = idx & 63;
            Bs[kk2][d] = Vp[(size_t)(k0 + kk2) * Ee + d];
        }
        __syncthreads();
#pragma unroll
        for (int kk = 0; kk < 16; kk++) {
            float a[4], bb[4];
#pragma unroll
            for (int i = 0; i < 4; i++) a[i] = As[kk][tm * 4 + i];
#pragma unroll
            for (int j = 0; j < 4; j++) bb[j] = Bs[kk][tn * 4 + j];
#pragma unroll
            for (int i = 0; i < 4; i++)
#pragma unroll
                for (int j = 0; j < 4; j++) acc[i][j] += a[i] * bb[j];
        }
        __syncthreads();
    }
#pragma unroll
    for (int i = 0; i < 4; i++)
#pragma unroll
        for (int j = 0; j < 4; j++) {
            int m = bm + tm * 4 + i, d = tn * 4 + j;
            Cp[(size_t)m * Ee + d] = acc[i][j];
        }
}

// ---------------- launch ----------------
extern "C" void kernel_launch(void* const* d_in, const int* in_sizes, int n_in,
                              void* d_out, int out_size)
{
    const float* x  = (const float*)d_in[0];
    const float* wq = (const float*)d_in[1];
    const float* bq = (const float*)d_in[2];
    const float* wk = (const float*)d_in[3];
    const float* bk = (const float*)d_in[4];
    const float* wv = (const float*)d_in[5];
    const float* bv = (const float*)d_in[6];
    const float* wo = (const float*)d_in[7];
    const float* bo = (const float*)d_in[8];
    const float* w1 = (const float*)d_in[9];
    const float* b1 = (const float*)d_in[10];
    const float* w2 = (const float*)d_in[11];
    const float* b2 = (const float*)d_in[12];
    float* out = (float*)d_out;

    void *pq, *pk, *pv, *pctx;
    cudaGetSymbolAddress(&pq, g_q);
    cudaGetSymbolAddress(&pk, g_k);
    cudaGetSymbolAddress(&pv, g_v);
    cudaGetSymbolAddress(&pctx, g_ctx);

    const float scaling = 0.125f;  // DH^-0.5

    dim3 gproj(Ee / 64, (Bb * Ss) / 64);
    gemm_proj<<<gproj, 256>>>(x, wq, bq, (float*)pq, scaling);
    gemm_proj<<<gproj, 256>>>(x, wk, bk, (float*)pk, 1.f);
    gemm_proj<<<gproj, 256>>>(x, wv, bv, (float*)pv, 1.f);

    dim3 gsc(Ss / 64, Ss / 64, Bb * Hh);
    gemm_scores<<<gsc, 256>>>();

    mean_heads_kernel<<<(Bb * Ss * Ss) / 256, 256>>>();
    transform_kernel<<<Bb * Ss, 512>>>(w1, b1, w2, b2);
    scalars_kernel<<<Bb, 512>>>();
    softmax_kernel<<<Bb * Hh * Ss, 256>>>();

    dim3 gav(Ss / 64, Bb * Hh);
    attnv_kernel<<<gav, 256>>>();

    gemm_proj<<<gproj, 256>>>((const float*)pctx, wo, bo, out, 1.f);
}

// round 2
// speedup vs baseline: 1.7236x; 1.7236x over previous
#include <cuda_runtime.h>
#include <math.h>

#define Bb   4
#define Ss   512
#define Ee   512
#define Hh   8
#define DHd  64
#define HIDh 128

// ---- scratch (allocation-free: __device__ globals) ----
__device__ float g_q[Bb*Ss*Ee];
__device__ float g_k[Bb*Ss*Ee];
__device__ float g_v[Bb*Ss*Ee];
__device__ float g_scores[(size_t)Bb*Hh*Ss*Ss];   // reused for probs
__device__ float g_tpre[(size_t)Bb*Ss*Ss];
__device__ float g_ctx[Bb*Ss*Ee];
__device__ float g_partial[Bb*Ss*4];
__device__ float g_Acoef[Bb];
__device__ float g_Ccoef[Bb];

// ---------------- reductions ----------------
__device__ __forceinline__ float warp_sum(float v) {
#pragma unroll
    for (int o = 16; o; o >>= 1) v += __shfl_xor_sync(0xffffffffu, v, o);
    return v;
}
__device__ __forceinline__ float warp_max(float v) {
#pragma unroll
    for (int o = 16; o; o >>= 1) v = fmaxf(v, __shfl_xor_sync(0xffffffffu, v, o));
    return v;
}
template <int NW>
__device__ __forceinline__ float block_sum(float v, float* red) {
    int lane = threadIdx.x & 31, w = threadIdx.x >> 5;
    v = warp_sum(v);
    if (lane == 0) red[w] = v;
    __syncthreads();
    if (w == 0) {
        float x = (lane < NW) ? red[lane] : 0.f;
        x = warp_sum(x);
        if (lane == 0) red[0] = x;
    }
    __syncthreads();
    float r = red[0];
    __syncthreads();
    return r;
}
template <int NW>
__device__ __forceinline__ float block_max(float v, float* red) {
    int lane = threadIdx.x & 31, w = threadIdx.x >> 5;
    v = warp_max(v);
    if (lane == 0) red[w] = v;
    __syncthreads();
    if (w == 0) {
        float x = (lane < NW) ? red[lane] : -3.402823e38f;
        x = warp_max(x);
        if (lane == 0) red[0] = x;
    }
    __syncthreads();
    float r = red[0];
    __syncthreads();
    return r;
}

// =====================================================================
// Tile engine: 128(M) x 64(N) block tile, 256 threads, 8x4 microtile.
// A: row-major [*, lda], k-contiguous.   (A pre-offset to bm row, B to bn row)
// NT: B row-major [n, ldb] k-contiguous (proj / scores).
// NN: B row-major [k, ldb] n-contiguous (attn*V).
// smem k-major with pad 4 -> float4 LDS on compute side.
// =====================================================================
__device__ __forceinline__ void mm_nt(
    const float* __restrict__ A, int lda,
    const float* __restrict__ B, int ldb,
    int K, int tid, float acc[8][4],
    float As[16][132], float Bs[16][68])
{
    int tm = tid >> 4, tn = tid & 15;
    for (int k0 = 0; k0 < K; k0 += 16) {
#pragma unroll
        for (int r = 0; r < 2; r++) {
            int f = tid + r * 256;
            int m = f >> 2, kq = (f & 3) << 2;
            const float4 av = *(const float4*)(A + (size_t)m * lda + k0 + kq);
            As[kq + 0][m] = av.x; As[kq + 1][m] = av.y;
            As[kq + 2][m] = av.z; As[kq + 3][m] = av.w;
        }
        {
            int n = tid >> 2, kq = (tid & 3) << 2;
            const float4 bv = *(const float4*)(B + (size_t)n * ldb + k0 + kq);
            Bs[kq + 0][n] = bv.x; Bs[kq + 1][n] = bv.y;
            Bs[kq + 2][n] = bv.z; Bs[kq + 3][n] = bv.w;
        }
        __syncthreads();
#pragma unroll
        for (int kk = 0; kk < 16; kk++) {
            float4 a0 = *(const float4*)&As[kk][tm * 8];
            float4 a1 = *(const float4*)&As[kk][tm * 8 + 4];
            float4 b0 = *(const float4*)&Bs[kk][tn * 4];
            float a[8] = {a0.x, a0.y, a0.z, a0.w, a1.x, a1.y, a1.z, a1.w};
            float b[4] = {b0.x, b0.y, b0.z, b0.w};
#pragma unroll
            for (int i = 0; i < 8; i++)
#pragma unroll
                for (int j = 0; j < 4; j++) acc[i][j] = fmaf(a[i], b[j], acc[i][j]);
        }
        __syncthreads();
    }
}

__device__ __forceinline__ void mm_nn(
    const float* __restrict__ A, int lda,
    const float* __restrict__ B, int ldb,
    int K, int tid, float acc[8][4],
    float As[16][132], float Bs[16][68])
{
    int tm = tid >> 4, tn = tid & 15;
    for (int k0 = 0; k0 < K; k0 += 16) {
#pragma unroll
        for (int r = 0; r < 2; r++) {
            int f = tid + r * 256;
            int m = f >> 2, kq = (f & 3) << 2;
            const float4 av = *(const float4*)(A + (size_t)m * lda + k0 + kq);
            As[kq + 0][m] = av.x; As[kq + 1][m] = av.y;
            As[kq + 2][m] = av.z; As[kq + 3][m] = av.w;
        }
        {
            int kk = tid >> 4, nq = (tid & 15) << 2;
            const float4 bv = *(const float4*)(B + (size_t)(k0 + kk) * ldb + nq);
            *(float4*)&Bs[kk][nq] = bv;
        }
        __syncthreads();
#pragma unroll
        for (int kk = 0; kk < 16; kk++) {
            float4 a0 = *(const float4*)&As[kk][tm * 8];
            float4 a1 = *(const float4*)&As[kk][tm * 8 + 4];
            float4 b0 = *(const float4*)&Bs[kk][tn * 4];
            float a[8] = {a0.x, a0.y, a0.z, a0.w, a1.x, a1.y, a1.z, a1.w};
            float b[4] = {b0.x, b0.y, b0.z, b0.w};
#pragma unroll
            for (int i = 0; i < 8; i++)
#pragma unroll
                for (int j = 0; j < 4; j++) acc[i][j] = fmaf(a[i], b[j], acc[i][j]);
        }
        __syncthreads();
    }
}

// ---------------- fused Q/K/V projection ----------------
// grid(24, 16): x -> 24 n-tiles over virtual N=1536 (q|k|v), y -> 16 m-tiles.
__global__ __launch_bounds__(256) void qkv_kernel(
    const float* __restrict__ x,
    const float* __restrict__ wq, const float* __restrict__ bq,
    const float* __restrict__ wk, const float* __restrict__ bk,
    const float* __restrict__ wv, const float* __restrict__ bv)
{
    __shared__ float As[16][132];
    __shared__ float Bs[16][68];
    int seg = blockIdx.x >> 3;          // 0=q 1=k 2=v
    int bn = (blockIdx.x & 7) * 64;
    int bm = blockIdx.y * 128;
    const float* W; const float* bias; float* C; float scale;
    if (seg == 0)      { W = wq; bias = bq; C = g_q; scale = 0.125f; }
    else if (seg == 1) { W = wk; bias = bk; C = g_k; scale = 1.f; }
    else               { W = wv; bias = bv; C = g_v; scale = 1.f; }

    int tid = threadIdx.x;
    float acc[8][4] = {};
    mm_nt(x + (size_t)bm * Ee, Ee, W + (size_t)bn * Ee, Ee, Ee, tid, acc, As, Bs);

    int tm = tid >> 4, tn = tid & 15;
    float4 bb = *(const float4*)(bias + bn + tn * 4);
#pragma unroll
    for (int i = 0; i < 8; i++) {
        int m = bm + tm * 8 + i;
        float4 o;
        o.x = (acc[i][0] + bb.x) * scale;
        o.y = (acc[i][1] + bb.y) * scale;
        o.z = (acc[i][2] + bb.z) * scale;
        o.w = (acc[i][3] + bb.w) * scale;
        *(float4*)(C + (size_t)m * Ee + bn + tn * 4) = o;
    }
}

// ---------------- output projection ----------------
// grid(8, 16)
__global__ __launch_bounds__(256) void oproj_kernel(
    const float* __restrict__ wo, const float* __restrict__ bo,
    float* __restrict__ out)
{
    __shared__ float As[16][132];
    __shared__ float Bs[16][68];
    int bn = blockIdx.x * 64;
    int bm = blockIdx.y * 128;
    int tid = threadIdx.x;
    float acc[8][4] = {};
    mm_nt(g_ctx + (size_t)bm * Ee, Ee, wo + (size_t)bn * Ee, Ee, Ee, tid, acc, As, Bs);

    int tm = tid >> 4, tn = tid & 15;
    float4 bb = *(const float4*)(bo + bn + tn * 4);
#pragma unroll
    for (int i = 0; i < 8; i++) {
        int m = bm + tm * 8 + i;
        float4 o;
        o.x = acc[i][0] + bb.x;
        o.y = acc[i][1] + bb.y;
        o.z = acc[i][2] + bb.z;
        o.w = acc[i][3] + bb.w;
        *(float4*)(out + (size_t)m * Ee + bn + tn * 4) = o;
    }
}

// ---------------- scores = clip(q k^T, -15, 15) ----------------
// grid(8, 4, 32)
__global__ __launch_bounds__(256) void scores_kernel()
{
    __shared__ float As[16][132];
    __shared__ float Bs[16][68];
    int bh = blockIdx.z;
    int b = bh >> 3, h = bh & 7;
    int bn = blockIdx.x * 64;
    int bm = blockIdx.y * 128;
    const float* Ap = g_q + ((size_t)b * Ss + bm) * Ee + h * DHd;
    const float* Bp = g_k + ((size_t)b * Ss + bn) * Ee + h * DHd;
    float* Cp = g_scores + (size_t)bh * Ss * Ss;

    int tid = threadIdx.x;
    float acc[8][4] = {};
    mm_nt(Ap, Ee, Bp, Ee, DHd, tid, acc, As, Bs);

    int tm = tid >> 4, tn = tid & 15;
#pragma unroll
    for (int i = 0; i < 8; i++) {
        int m = bm + tm * 8 + i;
        float4 o;
        o.x = fminf(fmaxf(acc[i][0], -15.f), 15.f);
        o.y = fminf(fmaxf(acc[i][1], -15.f), 15.f);
        o.z = fminf(fmaxf(acc[i][2], -15.f), 15.f);
        o.w = fminf(fmaxf(acc[i][3], -15.f), 15.f);
        *(float4*)(Cp + (size_t)m * Ss + bn + tn * 4) = o;
    }
}

// ---------------- transform (fused head-mean) ----------------
// grid Bb*Ss = 2048, block 512
__global__ __launch_bounds__(512) void transform_kernel(
    const float* __restrict__ w1, const float* __restrict__ b1,
    const float* __restrict__ w2, const float* __restrict__ b2p)
{
    __shared__ float red[16];
    __shared__ float sw1[HIDh], sb1[HIDh], sw2[HIDh];
    int row = blockIdx.x;            // b*Ss + i
    int b = row >> 9, i = row & (Ss - 1);
    int j = threadIdx.x;
    if (j < HIDh) { sw1[j] = w1[j]; sb1[j] = b1[j]; sw2[j] = w2[j]; }
    __syncthreads();

    // mean over heads
    float s = 0.f;
#pragma unroll
    for (int h = 0; h < Hh; h++)
        s += g_scores[(((size_t)(b * Hh + h)) * Ss + i) * Ss + j];
    float mv = s * 0.125f;

    // pointwise scalar function
    float scaled = fminf(fmaxf(mv, -8.f), 8.f) * 0.05f;
    float av = 0.f;
#pragma unroll 8
    for (int hh = 0; hh < HIDh; hh++) {
        float hv = fmaf(scaled, sw1[hh], sb1[hh]);
        hv = fminf(fmaxf(hv, 0.f), 5.f);
        av = fmaf(hv, sw2[hh], av);
    }
    av += b2p[0];
    av = fminf(fmaxf(av, -5.f), 5.f);
    float taylor = fminf(fmaxf(fmaf(av, 2.5f, 1.f), 0.5f), 1.5f);
    float sig = 1.f / (1.f + __expf(-taylor));

    // p = softmax(clip(mv)); entropy; Fm = softmax(3*H)
    float mc = fminf(fmaxf(mv, -10.f), 10.f);
    float M1 = block_max<16>(mc, red);
    float e1 = __expf(mc - M1);
    float S1 = block_sum<16>(e1, red);
    float p = e1 / S1;
    float Hent = -p * __logf(p + 1e-6f);
    float h3 = 3.f * Hent;
    float M2 = block_max<16>(h3, red);
    float e2 = __expf(h3 - M2);
    float S2 = block_sum<16>(e2, red);

    float t = sig * (e2 / S2);
    g_tpre[(size_t)row * Ss + j] = t;

    float s_m  = block_sum<16>(mv, red);
    float s_m2 = block_sum<16>(mv * mv, red);
    float s_t  = block_sum<16>(t, red);
    float s_t2 = block_sum<16>(t * t, red);
    if (j == 0) {
        g_partial[row * 4 + 0] = s_m;
        g_partial[row * 4 + 1] = s_m2;
        g_partial[row * 4 + 2] = s_t;
        g_partial[row * 4 + 3] = s_t2;
    }
}

// ---------------- per-batch scalars A,C ----------------
__global__ __launch_bounds__(512) void scalars_kernel()
{
    __shared__ float red[16];
    int b = blockIdx.x;
    int t = threadIdx.x;
    const float* pr = g_partial + (size_t)(b * Ss + t) * 4;
    float s0 = block_sum<16>(pr[0], red);
    float s1 = block_sum<16>(pr[1], red);
    float s2 = block_sum<16>(pr[2], red);
    float s3 = block_sum<16>(pr[3], red);
    if (t == 0) {
        const float N = (float)(Ss * Ss);
        float e_o = sqrtf(s1) + 1e-4f;
        float e_t = sqrtf(s3) + 1e-4f;
        float gamma = fminf(fmaxf(e_o / e_t, 0.8f), 1.2f);
        float mu_t = s2 / N, mu_o = s0 / N;
        float var_t = gamma * gamma * (s3 / N - mu_t * mu_t);
        float t_std = sqrtf(fmaxf(var_t, 0.01f));
        float var_o = s1 / N - mu_o * mu_o;
        float o_std = sqrtf(fmaxf(var_o, 0.01f));
        float gdyn = fminf(fmaxf(o_std / t_std, 0.8f), 1.2f);
        float A = gdyn * gamma;
        g_Acoef[b] = A;
        g_Ccoef[b] = mu_o - A * mu_t;
    }
}

// ---------------- blend + softmax (in place) ----------------
// grid Bb*Hh*Ss = 16384, block 256
__global__ __launch_bounds__(256) void softmax_kernel()
{
    __shared__ float red[8];
    __shared__ float sm[Ss];
    int rowid = blockIdx.x;
    int b = rowid >> 12;
    int i = rowid & (Ss - 1);
    float* srow = g_scores + (size_t)rowid * Ss;
    const float* trow = g_tpre + ((size_t)(b * Ss) + i) * Ss;
    float A = g_Acoef[b], C = g_Ccoef[b];

    float lm = -3.402823e38f;
    for (int j = threadIdx.x; j < Ss; j += 256) {
        float s = srow[j];
        float tt = fmaf(A, trow[j], C);
        s = fminf(fmaxf(fmaf(0.1f, tt, s), -15.f), 15.f);
        sm[j] = s;
        lm = fmaxf(lm, s);
    }
    float M = block_max<8>(lm, red);
    float ls = 0.f;
    for (int j = threadIdx.x; j < Ss; j += 256) {
        float e = __expf(sm[j] - M);
        sm[j] = e;
        ls += e;
    }
    float Sm = block_sum<8>(ls, red);
    float inv = 1.f / Sm;
    for (int j = threadIdx.x; j < Ss; j += 256)
        srow[j] = sm[j] * inv;
}

// ---------------- ctx = P @ V ----------------
// grid(4, 32): y-> m-tiles (128), z implicit via y? use (4, 32): x m-tile, y bh
__global__ __launch_bounds__(256) void attnv_kernel()
{
    __shared__ float As[16][132];
    __shared__ float Bs[16][68];
    int bh = blockIdx.y;
    int b = bh >> 3, h = bh & 7;
    int bm = blockIdx.x * 128;
    const float* Ap = g_scores + ((size_t)bh * Ss + bm) * Ss;
    const float* Bp = g_v + ((size_t)b * Ss) * Ee + h * DHd;
    float* Cp = g_ctx + ((size_t)b * Ss + bm) * Ee + h * DHd;

    int tid = threadIdx.x;
    float acc[8][4] = {};
    mm_nn(Ap, Ss, Bp, Ee, Ss, tid, acc, As, Bs);

    int tm = tid >> 4, tn = tid & 15;
#pragma unroll
    for (int i = 0; i < 8; i++) {
        int m = tm * 8 + i;
        float4 o;
        o.x = acc[i][0]; o.y = acc[i][1]; o.z = acc[i][2]; o.w = acc[i][3];
        *(float4*)(Cp + (size_t)m * Ee + tn * 4) = o;
    }
}

// ---------------- launch ----------------
extern "C" void kernel_launch(void* const* d_in, const int* in_sizes, int n_in,
                              void* d_out, int out_size)
{
    const float* x  = (const float*)d_in[0];
    const float* wq = (const float*)d_in[1];
    const float* bq = (const float*)d_in[2];
    const float* wk = (const float*)d_in[3];
    const float* bk = (const float*)d_in[4];
    const float* wv = (const float*)d_in[5];
    const float* bv = (const float*)d_in[6];
    const float* wo = (const float*)d_in[7];
    const float* bo = (const float*)d_in[8];
    const float* w1 = (const float*)d_in[9];
    const float* b1 = (const float*)d_in[10];
    const float* w2 = (const float*)d_in[11];
    const float* b2 = (const float*)d_in[12];
    float* out = (float*)d_out;

    qkv_kernel<<<dim3(24, 16), 256>>>(x, wq, bq, wk, bk, wv, bv);
    scores_kernel<<<dim3(8, 4, Bb * Hh), 256>>>();
    transform_kernel<<<Bb * Ss, 512>>>(w1, b1, w2, b2);
    scalars_kernel<<<Bb, 512>>>();
    softmax_kernel<<<Bb * Hh * Ss, 256>>>();
    attnv_kernel<<<dim3(4, Bb * Hh), 256>>>();
    oproj_kernel<<<dim3(8, 16), 256>>>(wo, bo, out);
}